// round 15
// baseline (speedup 1.0000x reference)
#include <cuda_runtime.h>
#include <cuda_fp16.h>
#include <cstdint>
#include <cstddef>

#define BB 32
#define TT 4096
#define HH 256
#define SS 256
#define MM (BB*TT)          // 131072 tokens
#define NCH 64              // chunks over T
#define LCH 64              // chunk length

// ---------------- scratch (static device globals; no allocations) ----------------
__device__ __half g_u[(size_t)MM*256];        // u (fp16)
__device__ __half g_wcat[(size_t)3*256*256];  // per-weight W (fp16)
__device__ float2 g_stats[(size_t)MM];        // per-row {mu, rs}
__device__ float g_carry[(size_t)BB*NCH*SS];
__device__ float g_S0[(size_t)BB*NCH*SS];
__device__ float g_coeff[SS];
__device__ float g_cL[SS];

// ---------------- helpers ----------------
__device__ __forceinline__ uint32_t smem_u32(const void* p) {
    uint32_t a;
    asm("{ .reg .u64 t; cvta.to.shared.u64 t, %1; cvt.u32.u64 %0, t; }" : "=r"(a) : "l"(p));
    return a;
}
__device__ __forceinline__ float softplus_f(float x) {
    return fmaxf(x, 0.0f) + log1pf(expf(-fabsf(x)));
}
__device__ __forceinline__ float tanh_fast(float x) {
    float y;
    asm("tanh.approx.f32 %0, %1;" : "=f"(y) : "f"(x));
    return y;
}
__device__ __forceinline__ float gelu_tanh(float x) {
    float x3 = x * x * x;
    float t = tanh_fast(0.7978845608028654f * (x + 0.044715f * x3));
    return 0.5f * x * (1.0f + t);
}
__device__ __forceinline__ unsigned pk2h(float a, float b) {
    __half2 t = __floats2half2_rn(a, b);
    return *reinterpret_cast<unsigned*>(&t);
}

#define CP_ASYNC16(saddr, gptr) \
    asm volatile("cp.async.cg.shared.global [%0], [%1], 16;" :: "r"(saddr), "l"(gptr))
#define CP_COMMIT() asm volatile("cp.async.commit_group;" ::: "memory")
#define CP_WAIT(n)  asm volatile("cp.async.wait_group %0;" :: "n"(n) : "memory")
#define LDMATRIX_X4(r, addr) \
    asm volatile("ldmatrix.sync.aligned.m8n8.x4.shared.b16 {%0,%1,%2,%3}, [%4];" \
        : "=r"((r)[0]), "=r"((r)[1]), "=r"((r)[2]), "=r"((r)[3]) : "r"(addr))
#define MMA_F16(d, a, b0, b1) \
    asm volatile("mma.sync.aligned.m16n8k16.row.col.f32.f16.f16.f32 " \
        "{%0,%1,%2,%3}, {%4,%5,%6,%7}, {%8,%9}, {%0,%1,%2,%3};" \
        : "+f"((d)[0]), "+f"((d)[1]), "+f"((d)[2]), "+f"((d)[3]) \
        : "r"((a)[0]), "r"((a)[1]), "r"((a)[2]), "r"((a)[3]), "r"(b0), "r"(b1))

// ---------------- 0. wsplit (fp16) + coefficients ----------------
__global__ void wsplit_kernel(const float* __restrict__ its,
                              const float* __restrict__ sth,
                              const float* __restrict__ ow,
                              const float* __restrict__ a_diag,
                              const float* __restrict__ g_diag,
                              const float* __restrict__ dt) {
    int widx = blockIdx.y;
    int n = blockIdx.x;
    int k = threadIdx.x;
    if (widx == 0 && n == 0) {
        int s = k;
        float dt_s = softplus_f(dt[s]) + 1e-4f;
        float omega = a_diag[s] * dt_s;
        float decay = expf(-softplus_f(g_diag[s]) * dt_s);
        decay *= decay;
        float c = decay * cosf(omega);
        g_coeff[s] = c;
        float p = c;
        #pragma unroll
        for (int i = 0; i < 6; i++) p = p * p;
        g_cL[s] = p;
    }
    const float* W = (widx == 0) ? its : ((widx == 1) ? sth : ow);
    g_wcat[(size_t)widx * 256 * 256 + (size_t)n * 256 + k] = __float2half_rn(W[n * 256 + k]);
}

// ---------------- 1. gemm0 with fused coalesced LayerNorm ----------------------------
// BM=64, BN=256, 256 thr, 2 CTAs/SM. SMEM (bytes):
//   A slots  : c*9216, c=0..3 (64x72 fp16)
//   W slot0  : 36864 (256x72 fp16), W slot1: 73728
//   X slot0  : 0     (64x68 fp32, overlays A0/A1 region; dead before A0/A1 written)
//   X slot1  : 73728 (overlays W slot1; w1 issued only after X1 dead)
// Pass1: stage x fp32 chunks coalescedly, accumulate row stats from SMEM.
// Pass2: normalize chunks -> fp16 A slots (c2,c3 resident; c0,c1 reloaded via L2).
// Mainloop: A resident, W double-buffered. Epilogue: u fp16 + fused chunk carries.
#define ASL   9216
#define WSL0  36864
#define X1OFF 73728
#define GSMEM0 110592
__global__ void __launch_bounds__(256, 2) gemm0_kernel(
    const float* __restrict__ x,
    const float* __restrict__ norm_w,
    const float* __restrict__ norm_b,
    const __half* __restrict__ W,
    __half* __restrict__ Cb,
    float2* __restrict__ stats)
{
    extern __shared__ __half smem[];
    char* smc = reinterpret_cast<char*>(smem);
    const uint32_t sbase = smem_u32(smem);
    const int tid = threadIdx.x;
    const int lane = tid & 31, wid = tid >> 5;
    const int wm = wid & 1, wn = wid >> 1;
    const size_t mblock = (size_t)blockIdx.x * 64;

    // x loader: chunk = 64 rows x 64 fp32, [64][68] padded
    const int xlr = tid >> 4;            // 0..15 (+16 per p)
    const int xls = tid & 15;            // float4 seg
    auto issue_x = [&](int c) {
        const uint32_t xo = (c & 1) ? X1OFF : 0u;
        const float* gx = x + (mblock + xlr) * 256 + c * 64 + xls * 4;
        #pragma unroll
        for (int p = 0; p < 4; p++)
            CP_ASYNC16(sbase + xo + ((xlr + p * 16) * 68 + xls * 4) * 4,
                       gx + (size_t)p * 16 * 256);
        CP_COMMIT();
    };

    // W loader: chunk = 256 rows x 64 fp16
    const int lrow = tid >> 3;
    const int lseg = (tid & 7) * 8;
    const __half* gW0 = W + (size_t)lrow * 256 + lseg;
    const uint32_t sWw = sbase + WSL0 + (lrow * 72 + lseg) * 2;
    auto issue_w = [&](int s) {
        const uint32_t so = (uint32_t)(s & 1) * 36864u;
        #pragma unroll
        for (int p = 0; p < 8; p++)
            CP_ASYNC16(sWw + so + p * 4608, gW0 + (size_t)p * 32 * 256 + s * 64);
        CP_COMMIT();
    };

    // stats / convert mapping: row = tid>>2, part = tid&3 (16 cols each)
    const int srow = tid >> 2, spart = tid & 3;
    float sum = 0.0f, sq = 0.0f;
    auto accum = [&](int c) {
        const float* xp = reinterpret_cast<const float*>(smc + ((c & 1) ? X1OFF : 0))
                          + srow * 68 + spart * 16;
        #pragma unroll
        for (int i = 0; i < 4; i++) {
            float4 v = *reinterpret_cast<const float4*>(xp + i * 4);
            sum += v.x + v.y + v.z + v.w;
            sq  += v.x*v.x + v.y*v.y + v.z*v.z + v.w*v.w;
        }
    };
    auto readx = [&](int c, float* r) {
        const float* xp = reinterpret_cast<const float*>(smc + ((c & 1) ? X1OFF : 0))
                          + srow * 68 + spart * 16;
        #pragma unroll
        for (int i = 0; i < 4; i++)
            *reinterpret_cast<float4*>(r + i * 4) =
                *reinterpret_cast<const float4*>(xp + i * 4);
    };

    // ---- pass 1: stats ----
    issue_x(0);                               // G0
    issue_x(1);                               // G1
    CP_WAIT(1); __syncthreads();
    accum(0);
    CP_WAIT(0); __syncthreads();              // X1 ready; X0 readers done
    issue_x(2);                               // G2 -> X0
    accum(1);
    __syncthreads();                          // X1 readers done
    issue_x(3);                               // G3 -> X1
    issue_w(0);                               // G4 -> W slot0
    CP_WAIT(2); __syncthreads();              // G2 done
    accum(2);
    CP_WAIT(1); __syncthreads();              // G3 done
    accum(3);

    sum += __shfl_xor_sync(0xffffffffu, sum, 1);
    sum += __shfl_xor_sync(0xffffffffu, sum, 2);
    sq  += __shfl_xor_sync(0xffffffffu, sq,  1);
    sq  += __shfl_xor_sync(0xffffffffu, sq,  2);
    const float mu = sum * (1.0f / 256.0f);
    const float var = sq * (1.0f / 256.0f) - mu * mu;
    const float rs = rsqrtf(var + 1e-5f);

    auto writeA = [&](int c, const float* r) {
        const float4* nw4 = reinterpret_cast<const float4*>(norm_w + c * 64 + spart * 16);
        const float4* nb4 = reinterpret_cast<const float4*>(norm_b + c * 64 + spart * 16);
        unsigned o[8];
        #pragma unroll
        for (int i = 0; i < 4; i++) {
            float4 wv = nw4[i], bv = nb4[i];
            float r0 = (r[i*4+0] - mu) * rs * wv.x + bv.x;
            float r1 = (r[i*4+1] - mu) * rs * wv.y + bv.y;
            float r2 = (r[i*4+2] - mu) * rs * wv.z + bv.z;
            float r3 = (r[i*4+3] - mu) * rs * wv.w + bv.w;
            o[i*2]   = pk2h(r0, r1);
            o[i*2+1] = pk2h(r2, r3);
        }
        uint4* dst = reinterpret_cast<uint4*>(smc + c * ASL + (srow * 72 + spart * 16) * 2);
        dst[0] = make_uint4(o[0], o[1], o[2], o[3]);
        dst[1] = make_uint4(o[4], o[5], o[6], o[7]);
    };

    // ---- pass 2: normalize -> A slots ----
    {
        float r23[32];
        readx(2, r23); readx(3, r23 + 16);
        __syncthreads();                      // X reads done
        writeA(2, r23); writeA(3, r23 + 16);  // A2/A3 disjoint from X0/X1
    }
    if (spart == 0) stats[mblock + srow] = make_float2(mu, rs);
    issue_x(0);                               // G5 -> X0 (overlays unwritten A0/A1)
    issue_x(1);                               // G6 -> X1 (W slot1 region; w1 not yet issued)
    {
        float r01[32];
        CP_WAIT(1); __syncthreads();          // G5 done (forces G4/w0 too)
        readx(0, r01);
        CP_WAIT(0); __syncthreads();          // G6 done
        readx(1, r01 + 16);
        __syncthreads();                      // X reads done
        writeA(0, r01); writeA(1, r01 + 16);  // overwrites X0 region (dead)
    }
    issue_w(1);                               // G7 -> W slot1 (X1 dead)

    // ---- mainloop: A resident, W double-buffered ----
    const uint32_t a_rel = ((wm * 32 + (lane & 15)) * 72 + (lane >> 4) * 8) * 2;
    const uint32_t b_off = sbase + WSL0 +
        ((wn * 64 + ((lane >> 3) & 1) * 8 + (lane & 7)) * 72 + (lane >> 4) * 8) * 2;

    float acc[2][8][4];
    #pragma unroll
    for (int i = 0; i < 2; i++)
        #pragma unroll
        for (int j = 0; j < 8; j++)
            #pragma unroll
            for (int q = 0; q < 4; q++) acc[i][j][q] = 0.0f;

    auto mma_step = [&](uint32_t ab, uint32_t bb) {
        #pragma unroll
        for (int ks = 0; ks < 4; ks++) {
            uint32_t af[2][4];
            LDMATRIX_X4(af[0], ab + ks * 32);
            LDMATRIX_X4(af[1], ab + 2304 + ks * 32);
            uint32_t bf[4][4];
            #pragma unroll
            for (int q = 0; q < 4; q++) LDMATRIX_X4(bf[q], bb + q * 2304 + ks * 32);
            #pragma unroll
            for (int mt = 0; mt < 2; mt++)
                #pragma unroll
                for (int nt = 0; nt < 8; nt++) {
                    const int q = nt >> 1, od = nt & 1;
                    MMA_F16(acc[mt][nt], af[mt], bf[q][od], bf[q][2 + od]);
                }
        }
    };

    #pragma unroll
    for (int s = 0; s < 4; s++) {
        if (s > 0) { CP_WAIT(0); }
        __syncthreads();
        mma_step(sbase + (uint32_t)s * ASL + a_rel, b_off + (uint32_t)(s & 1) * 36864u);
        if (s >= 1 && s < 3) {
            __syncthreads();                  // W slot (s-1)&1 readers done
            issue_w(s + 1);
        }
    }

    // ---- epilogue: u fp16 + staged fp32 tile -> fused chunk carries ----
    __syncthreads();
    float* su = reinterpret_cast<float*>(smem);   // [64][256] fp32 (65536 B)

    #pragma unroll
    for (int mt = 0; mt < 2; mt++) {
        #pragma unroll
        for (int h = 0; h < 2; h++) {
            const int ml = wm * 32 + mt * 16 + (lane >> 2) + h * 8;
            const size_t mg = mblock + ml;
            #pragma unroll
            for (int nt = 0; nt < 8; nt++) {
                const int nl = wn * 64 + nt * 8 + (lane & 3) * 2;
                float v0 = acc[mt][nt][h * 2], v1 = acc[mt][nt][h * 2 + 1];
                *reinterpret_cast<uint32_t*>(Cb + mg * 256 + nl) = pk2h(v0, v1);
                float2 o; o.x = v0; o.y = v1;
                *reinterpret_cast<float2*>(su + ml * 256 + nl) = o;
            }
        }
    }

    __syncthreads();
    {
        const float cc = g_coeff[tid];
        const float* col = su + tid;
        float a = 0.0f;
        #pragma unroll 16
        for (int j = 0; j < 64; j++) a = fmaf(cc, a, col[j * 256]);
        const int b = (int)(mblock >> 12);
        const int chg = (int)(blockIdx.x & 63);
        g_carry[((size_t)b * NCH + chg) * SS + tid] = a;
    }
}

// ---------------- 2b. gemm12: BM=64, 256 thr, 2 CTAs/SM (xn recomputed) -----------
#define ASLOT 9216
#define WB    (4*ASLOT)
#define WS2   36864
#define GSMEM12 (WB + 2*WS2)
__global__ void __launch_bounds__(256, 2) gemm12_kernel(
    const __half* __restrict__ U,
    const __half* __restrict__ W1,
    const __half* __restrict__ W2,
    const float* __restrict__ direct,
    const float2* __restrict__ stats,
    const float* __restrict__ norm_w,
    const float* __restrict__ norm_b,
    const float* __restrict__ x,
    const float* __restrict__ out_b,
    float* __restrict__ out)
{
    extern __shared__ __half smem[];
    const uint32_t sbase = smem_u32(smem);
    const int tid = threadIdx.x;
    const int lane = tid & 31, wid = tid >> 5;
    const int wm = wid & 1, wn = wid >> 1;
    const size_t mblock = (size_t)blockIdx.x * 64;

    const int arow = tid >> 3;
    const int aseg = (tid & 7) * 8;
    const __half* gU  = U  + (mblock + arow) * 256 + aseg;
    const __half* gW1 = W1 + (size_t)arow * 256 + aseg;
    const __half* gW2 = W2 + (size_t)arow * 256 + aseg;
    const uint32_t sAw = sbase + (arow * 72 + aseg) * 2;
    const uint32_t sWw = sbase + WB + (arow * 72 + aseg) * 2;

    const uint32_t a_rel = ((wm * 32 + (lane & 15)) * 72 + (lane >> 4) * 8) * 2;
    const uint32_t b_off = sbase + WB +
        ((wn * 64 + ((lane >> 3) & 1) * 8 + (lane & 7)) * 72 + (lane >> 4) * 8) * 2;

    const int sc = tid & 63;
    const bool scanner = tid < 64;
    float s0v[4], cfv[4];
    if (scanner) {
        const int bidx = (int)(mblock >> 12);
        const int chg = (int)((mblock & 4095) >> 6);
        #pragma unroll
        for (int s = 0; s < 4; s++) {
            const int scol = s * 64 + sc;
            cfv[s] = g_coeff[scol];
            s0v[s] = g_S0[((size_t)bidx * NCH + chg) * SS + scol];
        }
    }

    float acc[2][8][4];
    #pragma unroll
    for (int i = 0; i < 2; i++)
        #pragma unroll
        for (int j = 0; j < 8; j++)
            #pragma unroll
            for (int q = 0; q < 4; q++) acc[i][j][q] = 0.0f;

    auto issue_u = [&](int s) {
        const uint32_t so = (uint32_t)(s & 1) * ASLOT;
        #pragma unroll
        for (int p = 0; p < 2; p++)
            CP_ASYNC16(sAw + so + p * 4608, gU + (size_t)p * 32 * 256 + s * 64);
    };
    auto issue_w = [&](const __half* gWb, int s) {
        const uint32_t so = (uint32_t)(s & 1) * WS2;
        #pragma unroll
        for (int p = 0; p < 8; p++)
            CP_ASYNC16(sWw + so + p * 4608, gWb + (size_t)p * 32 * 256 + s * 64);
    };
    auto scan = [&](int s) {
        if (scanner) {
            __half* ap = smem + (size_t)(s & 1) * (ASLOT / 2) + sc;
            float run = s0v[s];
            const float cc = cfv[s];
            #pragma unroll
            for (int j = 0; j < 64; j++) {
                run = fmaf(cc, run, __half2float(ap[j * 72]));
                ap[j * 72] = __float2half_rn(run);
            }
        }
    };
    auto mma_step = [&](uint32_t ab, uint32_t bb) {
        #pragma unroll
        for (int ks = 0; ks < 4; ks++) {
            uint32_t af[2][4];
            LDMATRIX_X4(af[0], ab + ks * 32);
            LDMATRIX_X4(af[1], ab + 2304 + ks * 32);
            uint32_t bf[4][4];
            #pragma unroll
            for (int q = 0; q < 4; q++) LDMATRIX_X4(bf[q], bb + q * 2304 + ks * 32);
            #pragma unroll
            for (int mt = 0; mt < 2; mt++)
                #pragma unroll
                for (int nt = 0; nt < 8; nt++) {
                    const int q = nt >> 1, od = nt & 1;
                    MMA_F16(acc[mt][nt], af[mt], bf[q][od], bf[q][2 + od]);
                }
        }
    };

    // ---- phase 1 ----
    issue_u(0); issue_w(gW1, 0); CP_COMMIT();
    issue_u(1); issue_w(gW1, 1); CP_COMMIT();
    CP_WAIT(1);
    __syncthreads();
    scan(0);

    #pragma unroll
    for (int s = 0; s < 4; s++) {
        __syncthreads();
        mma_step(sbase + (uint32_t)(s & 1) * ASLOT + a_rel,
                 b_off + (uint32_t)(s & 1) * WS2);
        __syncthreads();
        if (s < 2) { issue_u(s + 2); issue_w(gW1, s + 2); CP_COMMIT(); }
        if (s < 3) {
            if (s < 2) { CP_WAIT(1); } else { CP_WAIT(0); }
            __syncthreads();
            scan(s + 1);
        }
    }

    issue_w(gW2, 0); CP_COMMIT();
    issue_w(gW2, 1); CP_COMMIT();

    // ---- epilogue 1: mix = gelu(acc + direct * xn(x, stats)) -> SMEM ----
    char* smc = reinterpret_cast<char*>(smem);
    #pragma unroll
    for (int mt = 0; mt < 2; mt++) {
        #pragma unroll
        for (int h = 0; h < 2; h++) {
            const int ml = wm * 32 + mt * 16 + (lane >> 2) + h * 8;
            const size_t mg = mblock + ml;
            const float2 st = stats[mg];
            #pragma unroll
            for (int nt = 0; nt < 8; nt++) {
                const int nl = wn * 64 + nt * 8 + (lane & 3) * 2;
                float v0 = acc[mt][nt][h * 2], v1 = acc[mt][nt][h * 2 + 1];
                float2 xv = *reinterpret_cast<const float2*>(x + mg * 256 + nl);
                float2 nwv = *reinterpret_cast<const float2*>(norm_w + nl);
                float2 nbv = *reinterpret_cast<const float2*>(norm_b + nl);
                float2 dd = *reinterpret_cast<const float2*>(direct + nl);
                float xn0 = (xv.x - st.x) * st.y * nwv.x + nbv.x;
                float xn1 = (xv.y - st.x) * st.y * nwv.y + nbv.y;
                float o0 = gelu_tanh(v0 + dd.x * xn0);
                float o1 = gelu_tanh(v1 + dd.y * xn1);
                *reinterpret_cast<uint32_t*>(
                    smc + (nl >> 6) * ASLOT + (ml * 72 + (nl & 63)) * 2) = pk2h(o0, o1);
            }
        }
    }

    #pragma unroll
    for (int i = 0; i < 2; i++)
        #pragma unroll
        for (int j = 0; j < 8; j++)
            #pragma unroll
            for (int q = 0; q < 4; q++) acc[i][j][q] = 0.0f;

    // ---- phase 2: mix (SMEM, slot s) x W2 (double-buffered) ----
    #pragma unroll
    for (int s = 0; s < 4; s++) {
        if (s < 3) { CP_WAIT(1); } else { CP_WAIT(0); }
        __syncthreads();
        mma_step(sbase + (uint32_t)s * ASLOT + a_rel,
                 b_off + (uint32_t)(s & 1) * WS2);
        if (s < 2) {
            __syncthreads();
            issue_w(gW2, s + 2); CP_COMMIT();
        }
    }

    // ---- epilogue 2: out = x + acc + out_b ----
    #pragma unroll
    for (int mt = 0; mt < 2; mt++) {
        #pragma unroll
        for (int h = 0; h < 2; h++) {
            const size_t mg = mblock + wm * 32 + mt * 16 + (lane >> 2) + h * 8;
            #pragma unroll
            for (int nt = 0; nt < 8; nt++) {
                const int n = wn * 64 + nt * 8 + (lane & 3) * 2;
                float v0 = acc[mt][nt][h * 2], v1 = acc[mt][nt][h * 2 + 1];
                float2 xv = *reinterpret_cast<const float2*>(x + mg * 256 + n);
                float2 bb2 = *reinterpret_cast<const float2*>(out_b + n);
                float2 o;
                o.x = xv.x + v0 + bb2.x;
                o.y = xv.y + v1 + bb2.y;
                *reinterpret_cast<float2*>(out + mg * 256 + n) = o;
            }
        }
    }
}

// ---------------- 3b. chunk-level scan (prefetch all carries) ----------------
__global__ void __launch_bounds__(256) scanB_kernel(const float* __restrict__ state0,
                                                    float* __restrict__ out) {
    int b = blockIdx.x, s = threadIdx.x;
    const float* cp = g_carry + (size_t)b * NCH * SS + s;
    float carr[NCH];
    #pragma unroll
    for (int ch = 0; ch < NCH; ch++) carr[ch] = cp[(size_t)ch * SS];
    float cL = g_cL[s];
    float run = state0[b * SS + s];
    float* s0 = g_S0 + (size_t)b * NCH * SS + s;
    #pragma unroll
    for (int ch = 0; ch < NCH; ch++) {
        s0[(size_t)ch * SS] = run;
        run = fmaf(cL, run, carr[ch]);
    }
    out[(size_t)MM * HH + (size_t)b * SS + s] = run;
}

// ---------------- launch ----------------
extern "C" void kernel_launch(void* const* d_in, const int* in_sizes, int n_in,
                              void* d_out, int out_size) {
    const float* x       = (const float*)d_in[0];
    const float* state0  = (const float*)d_in[1];
    const float* its     = (const float*)d_in[2];
    const float* sth     = (const float*)d_in[3];
    const float* direct  = (const float*)d_in[4];
    const float* a_diag  = (const float*)d_in[5];
    const float* g_diag  = (const float*)d_in[6];
    const float* dt      = (const float*)d_in[7];
    const float* norm_w  = (const float*)d_in[8];
    const float* norm_b  = (const float*)d_in[9];
    const float* out_w   = (const float*)d_in[10];
    const float* out_b   = (const float*)d_in[11];
    float* out = (float*)d_out;

    __half *u16, *wcat;
    float2* stats;
    cudaGetSymbolAddress((void**)&u16,   g_u);
    cudaGetSymbolAddress((void**)&wcat,  g_wcat);
    cudaGetSymbolAddress((void**)&stats, g_stats);

    cudaFuncSetAttribute(gemm0_kernel, cudaFuncAttributeMaxDynamicSharedMemorySize, GSMEM0);
    cudaFuncSetAttribute(gemm12_kernel, cudaFuncAttributeMaxDynamicSharedMemorySize, GSMEM12);

    wsplit_kernel<<<dim3(256, 3), 256>>>(its, sth, out_w, a_diag, g_diag, dt);

    gemm0_kernel<<<MM / 64, 256, GSMEM0>>>(x, norm_w, norm_b, wcat, u16, stats);

    scanB_kernel<<<BB, 256>>>(state0, out);

    gemm12_kernel<<<MM / 64, 256, GSMEM12>>>(
        u16, wcat + (size_t)1 * 256 * 256, wcat + (size_t)2 * 256 * 256,
        direct, stats, norm_w, norm_b, x, out_b, out);
}

// round 16
// speedup vs baseline: 1.0629x; 1.0629x over previous
#include <cuda_runtime.h>
#include <cuda_fp16.h>
#include <cstdint>
#include <cstddef>

#define BB 32
#define TT 4096
#define HH 256
#define SS 256
#define MM (BB*TT)          // 131072 tokens
#define NCH 64              // chunks over T
#define LCH 64              // chunk length

// ---------------- scratch (static device globals; no allocations) ----------------
__device__ __half g_xn[(size_t)MM*256];       // layernormed x (fp16)
__device__ __half g_u[(size_t)MM*256];        // u (fp16)
__device__ __half g_wcat[(size_t)3*256*256];  // per-weight W (fp16)
__device__ float g_carry[(size_t)BB*NCH*SS];
__device__ float g_S0[(size_t)BB*NCH*SS];
__device__ float g_coeff[SS];
__device__ float g_cL[SS];

// ---------------- helpers ----------------
__device__ __forceinline__ uint32_t smem_u32(const void* p) {
    uint32_t a;
    asm("{ .reg .u64 t; cvta.to.shared.u64 t, %1; cvt.u32.u64 %0, t; }" : "=r"(a) : "l"(p));
    return a;
}
__device__ __forceinline__ float softplus_f(float x) {
    return fmaxf(x, 0.0f) + log1pf(expf(-fabsf(x)));
}
__device__ __forceinline__ float tanh_fast(float x) {
    float y;
    asm("tanh.approx.f32 %0, %1;" : "=f"(y) : "f"(x));
    return y;
}
__device__ __forceinline__ float gelu_tanh(float x) {
    float x3 = x * x * x;
    float t = tanh_fast(0.7978845608028654f * (x + 0.044715f * x3));
    return 0.5f * x * (1.0f + t);
}
__device__ __forceinline__ unsigned pk2h(float a, float b) {
    __half2 t = __floats2half2_rn(a, b);
    return *reinterpret_cast<unsigned*>(&t);
}

#define CP_ASYNC16(saddr, gptr) \
    asm volatile("cp.async.cg.shared.global [%0], [%1], 16;" :: "r"(saddr), "l"(gptr))
#define CP_COMMIT() asm volatile("cp.async.commit_group;" ::: "memory")
#define CP_WAIT(n)  asm volatile("cp.async.wait_group %0;" :: "n"(n) : "memory")
#define LDMATRIX_X4(r, addr) \
    asm volatile("ldmatrix.sync.aligned.m8n8.x4.shared.b16 {%0,%1,%2,%3}, [%4];" \
        : "=r"((r)[0]), "=r"((r)[1]), "=r"((r)[2]), "=r"((r)[3]) : "r"(addr))
#define MMA_F16(d, a, b0, b1) \
    asm volatile("mma.sync.aligned.m16n8k16.row.col.f32.f16.f16.f32 " \
        "{%0,%1,%2,%3}, {%4,%5,%6,%7}, {%8,%9}, {%0,%1,%2,%3};" \
        : "+f"((d)[0]), "+f"((d)[1]), "+f"((d)[2]), "+f"((d)[3]) \
        : "r"((a)[0]), "r"((a)[1]), "r"((a)[2]), "r"((a)[3]), "r"(b0), "r"(b1))

#define GSLOT 18432

// ---------------- 0. wsplit (fp16) + coefficients ----------------
__global__ void wsplit_kernel(const float* __restrict__ its,
                              const float* __restrict__ sth,
                              const float* __restrict__ ow,
                              const float* __restrict__ a_diag,
                              const float* __restrict__ g_diag,
                              const float* __restrict__ dt) {
    int widx = blockIdx.y;
    int n = blockIdx.x;
    int k = threadIdx.x;
    if (widx == 0 && n == 0) {
        int s = k;
        float dt_s = softplus_f(dt[s]) + 1e-4f;
        float omega = a_diag[s] * dt_s;
        float decay = expf(-softplus_f(g_diag[s]) * dt_s);
        decay *= decay;
        float c = decay * cosf(omega);
        g_coeff[s] = c;
        float p = c;
        #pragma unroll
        for (int i = 0; i < 6; i++) p = p * p;
        g_cL[s] = p;
    }
    const float* W = (widx == 0) ? its : ((widx == 1) ? sth : ow);
    g_wcat[(size_t)widx * 256 * 256 + (size_t)n * 256 + k] = __float2half_rn(W[n * 256 + k]);
}

// ---------------- 1. layernorm -> fp16 (coalesced, warp per row) ----------------
__global__ void __launch_bounds__(256) ln_kernel(const float* __restrict__ x,
                                                 const float* __restrict__ w,
                                                 const float* __restrict__ b) {
    int warp = threadIdx.x >> 5, lane = threadIdx.x & 31;
    size_t row = (size_t)blockIdx.x * 8 + warp;
    const float4* xr = reinterpret_cast<const float4*>(x + row * HH);
    float4 v0 = xr[lane];
    float4 v1 = xr[lane + 32];
    float sum = v0.x + v0.y + v0.z + v0.w + v1.x + v1.y + v1.z + v1.w;
    float sq  = v0.x*v0.x + v0.y*v0.y + v0.z*v0.z + v0.w*v0.w
              + v1.x*v1.x + v1.y*v1.y + v1.z*v1.z + v1.w*v1.w;
    #pragma unroll
    for (int o = 16; o > 0; o >>= 1) {
        sum += __shfl_xor_sync(0xffffffffu, sum, o);
        sq  += __shfl_xor_sync(0xffffffffu, sq,  o);
    }
    float mu = sum * (1.0f / HH);
    float var = sq * (1.0f / HH) - mu * mu;
    float rs = rsqrtf(var + 1e-5f);

    const float4* w4 = reinterpret_cast<const float4*>(w);
    const float4* b4 = reinterpret_cast<const float4*>(b);
    __half* dst = g_xn + row * 256;

    #pragma unroll
    for (int half_ = 0; half_ < 2; half_++) {
        float4 v = half_ ? v1 : v0;
        int c0 = half_ * 128 + lane * 4;
        float4 wv = w4[half_ * 32 + lane], bv = b4[half_ * 32 + lane];
        float r0 = (v.x - mu) * rs * wv.x + bv.x;
        float r1 = (v.y - mu) * rs * wv.y + bv.y;
        float r2 = (v.z - mu) * rs * wv.z + bv.z;
        float r3 = (v.w - mu) * rs * wv.w + bv.w;
        uint2 hv;
        hv.x = pk2h(r0, r1);
        hv.y = pk2h(r2, r3);
        *reinterpret_cast<uint2*>(dst + c0) = hv;
    }
}

// ---------------- 2. gemm0: xn x W0 -> u fp16 + fused chunk carries ----------------
#define GSMEM0 (6*GSLOT)
__global__ void __launch_bounds__(256, 2) gemm0_kernel(
    const __half* __restrict__ A,
    const __half* __restrict__ W,
    __half* __restrict__ Cb)
{
    extern __shared__ __half smem[];
    const uint32_t sbase = smem_u32(smem);
    const int tid = threadIdx.x;
    const int lane = tid & 31, wid = tid >> 5;
    const int wm = wid & 3, wn = wid >> 2;
    const size_t mblock = (size_t)blockIdx.y * 128;
    const int nblock = blockIdx.x * 128;

    const int lrow = tid >> 3;
    const int lseg = (tid & 7) * 8;
    const __half* gA = A + (mblock + lrow) * 256 + lseg;
    const __half* gW = W + (size_t)(nblock + lrow) * 256 + lseg;
    const uint32_t sAw = sbase + (lrow * 72 + lseg) * 2;
    const uint32_t sBw = sbase + 3*GSLOT + (lrow * 72 + lseg) * 2;

    const uint32_t a_off = sbase + ((wm * 32 + (lane & 15)) * 72 + (lane >> 4) * 8) * 2;
    const uint32_t b_off = sbase + 3*GSLOT +
        ((wn * 64 + ((lane >> 3) & 1) * 8 + (lane & 7)) * 72 + (lane >> 4) * 8) * 2;

    float acc[2][8][4];
    #pragma unroll
    for (int i = 0; i < 2; i++)
        #pragma unroll
        for (int j = 0; j < 8; j++)
            #pragma unroll
            for (int q = 0; q < 4; q++) acc[i][j][q] = 0.0f;

    auto issue_step = [&](int s) {
        const uint32_t so = (uint32_t)(s % 3) * GSLOT;
        const int col = s * 64;
        #pragma unroll
        for (int p = 0; p < 4; p++)
            CP_ASYNC16(sAw + so + p * 4608, gA + (size_t)p * 32 * 256 + col);
        #pragma unroll
        for (int p = 0; p < 4; p++)
            CP_ASYNC16(sBw + so + p * 4608, gW + (size_t)p * 32 * 256 + col);
        CP_COMMIT();
    };

    issue_step(0);
    issue_step(1);

    #pragma unroll
    for (int s = 0; s < 4; s++) {
        if (s < 3) { CP_WAIT(1); } else { CP_WAIT(0); }
        __syncthreads();
        if (s < 2) issue_step(s + 2);
        const uint32_t ab = a_off + (uint32_t)(s % 3) * GSLOT;
        const uint32_t bb = b_off + (uint32_t)(s % 3) * GSLOT;
        #pragma unroll
        for (int ks = 0; ks < 4; ks++) {
            uint32_t af[2][4];
            LDMATRIX_X4(af[0], ab + ks * 32);
            LDMATRIX_X4(af[1], ab + 2304 + ks * 32);
            uint32_t bf[4][4];
            #pragma unroll
            for (int q = 0; q < 4; q++) LDMATRIX_X4(bf[q], bb + q * 2304 + ks * 32);
            #pragma unroll
            for (int mt = 0; mt < 2; mt++)
                #pragma unroll
                for (int nt = 0; nt < 8; nt++) {
                    const int q = nt >> 1, od = nt & 1;
                    MMA_F16(acc[mt][nt], af[mt], bf[q][od], bf[q][2 + od]);
                }
        }
    }

    __syncthreads();
    float* su = reinterpret_cast<float*>(smem);   // [128][128] u tile

    #pragma unroll
    for (int mt = 0; mt < 2; mt++) {
        #pragma unroll
        for (int h = 0; h < 2; h++) {
            const int ml = wm * 32 + mt * 16 + (lane >> 2) + h * 8;
            const size_t mg = mblock + ml;
            #pragma unroll
            for (int nt = 0; nt < 8; nt++) {
                const int nl = wn * 64 + nt * 8 + (lane & 3) * 2;
                const int n = nblock + nl;
                float v0 = acc[mt][nt][h * 2], v1 = acc[mt][nt][h * 2 + 1];
                *reinterpret_cast<uint32_t*>(Cb + mg * 256 + n) = pk2h(v0, v1);
                float2 o; o.x = v0; o.y = v1;
                *reinterpret_cast<float2*>(su + ml * 128 + nl) = o;
            }
        }
    }

    __syncthreads();
    const int s_loc = tid & 127;
    const int chl = tid >> 7;
    const int sg = nblock + s_loc;
    const float cc = g_coeff[sg];
    const float* col = su + chl * 64 * 128 + s_loc;
    float a = 0.0f;
    #pragma unroll 16
    for (int j = 0; j < 64; j++) a = fmaf(cc, a, col[j * 128]);
    const int b = (int)(mblock >> 12);
    const int chg = (int)((mblock & 4095) >> 6) + chl;
    g_carry[((size_t)b * NCH + chg) * SS + sg] = a;
}

// ---------------- 2b. gemm12: BM=64, 256 thr, 2 CTAs/SM; parallel up-front scan ----
// Phase 0: load ALL 4 u chunks into A slots 0..3; scan all 4 in parallel (256 thr:
//          chunk = tid>>6, col = tid&63).
// Phase 1: st (resident) x W1 (double-buffered) -> gelu(+direct*xn) -> mix in A slots.
// Phase 2: mix (SMEM) x W2 -> out = x + acc + out_b.
// SMEM: A slots c*9216 (c=0..3); W slots at 36864 + i*36864 (i=0,1). Total 110592 B.
#define ASLOT 9216
#define WB    (4*ASLOT)
#define WS2   36864
#define GSMEM12 (WB + 2*WS2)
__global__ void __launch_bounds__(256, 2) gemm12_kernel(
    const __half* __restrict__ U,
    const __half* __restrict__ W1,
    const __half* __restrict__ W2,
    const float* __restrict__ direct,
    const __half* __restrict__ xn,
    const float* __restrict__ x,
    const float* __restrict__ out_b,
    float* __restrict__ out)
{
    extern __shared__ __half smem[];
    const uint32_t sbase = smem_u32(smem);
    const int tid = threadIdx.x;
    const int lane = tid & 31, wid = tid >> 5;
    const int wm = wid & 1, wn = wid >> 1;       // 2 x 4 warps, warp tile 32x64
    const size_t mblock = (size_t)blockIdx.x * 64;

    const int arow = tid >> 3;                   // 0..31
    const int aseg = (tid & 7) * 8;
    const __half* gU  = U  + (mblock + arow) * 256 + aseg;
    const __half* gW1 = W1 + (size_t)arow * 256 + aseg;
    const __half* gW2 = W2 + (size_t)arow * 256 + aseg;
    const uint32_t sAw = sbase + (arow * 72 + aseg) * 2;
    const uint32_t sWw = sbase + WB + (arow * 72 + aseg) * 2;

    const uint32_t a_rel = ((wm * 32 + (lane & 15)) * 72 + (lane >> 4) * 8) * 2;
    const uint32_t b_off = sbase + WB +
        ((wn * 64 + ((lane >> 3) & 1) * 8 + (lane & 7)) * 72 + (lane >> 4) * 8) * 2;

    float acc[2][8][4];
    #pragma unroll
    for (int i = 0; i < 2; i++)
        #pragma unroll
        for (int j = 0; j < 8; j++)
            #pragma unroll
            for (int q = 0; q < 4; q++) acc[i][j][q] = 0.0f;

    auto issue_w = [&](const __half* gWb, int s) {
        const uint32_t so = (uint32_t)(s & 1) * WS2;
        #pragma unroll
        for (int p = 0; p < 8; p++)
            CP_ASYNC16(sWw + so + p * 4608, gWb + (size_t)p * 32 * 256 + s * 64);
        CP_COMMIT();
    };
    auto mma_step = [&](uint32_t ab, uint32_t bb) {
        #pragma unroll
        for (int ks = 0; ks < 4; ks++) {
            uint32_t af[2][4];
            LDMATRIX_X4(af[0], ab + ks * 32);
            LDMATRIX_X4(af[1], ab + 2304 + ks * 32);     // +16 rows
            uint32_t bf[4][4];
            #pragma unroll
            for (int q = 0; q < 4; q++) LDMATRIX_X4(bf[q], bb + q * 2304 + ks * 32);
            #pragma unroll
            for (int mt = 0; mt < 2; mt++)
                #pragma unroll
                for (int nt = 0; nt < 8; nt++) {
                    const int q = nt >> 1, od = nt & 1;
                    MMA_F16(acc[mt][nt], af[mt], bf[q][od], bf[q][2 + od]);
                }
        }
    };

    // ---- phase 0: load all u chunks (G0), W1 slots (G1, G2) ----
    #pragma unroll
    for (int s = 0; s < 4; s++) {
        #pragma unroll
        for (int p = 0; p < 2; p++)
            CP_ASYNC16(sAw + (uint32_t)s * ASLOT + p * 4608,
                       gU + (size_t)p * 32 * 256 + s * 64);
    }
    CP_COMMIT();                              // G0
    issue_w(gW1, 0);                          // G1
    issue_w(gW1, 1);                          // G2

    // scan all 4 chunks in parallel: chunk = tid>>6, col = tid&63
    {
        const int chunk = tid >> 6, sc = tid & 63;
        const int bidx = (int)(mblock >> 12);
        const int chg = (int)(blockIdx.x & 63);
        const int scol = chunk * 64 + sc;
        const float cc = g_coeff[scol];
        float run = g_S0[((size_t)bidx * NCH + chg) * SS + scol];
        CP_WAIT(2);                           // G0 (u) complete
        __syncthreads();
        __half* ap = smem + (size_t)chunk * (ASLOT / 2) + sc;
        #pragma unroll
        for (int j = 0; j < 64; j++) {
            run = fmaf(cc, run, __half2float(ap[j * 72]));
            ap[j * 72] = __float2half_rn(run);
        }
    }

    // ---- phase 1: st (resident A slots) x W1 (double-buffered) ----
    #pragma unroll
    for (int s = 0; s < 4; s++) {
        if (s < 3) { CP_WAIT(1); } else { CP_WAIT(0); }
        __syncthreads();                      // W visible + (s==0) scan writes visible
        mma_step(sbase + (uint32_t)s * ASLOT + a_rel, b_off + (uint32_t)(s & 1) * WS2);
        if (s < 2) {
            __syncthreads();                  // W slot s&1 readers done
            issue_w(gW1, s + 2);
        }
    }

    __syncthreads();                          // slot-3 readers done before mix overwrite
    issue_w(gW2, 0);
    issue_w(gW2, 1);

    // ---- epilogue 1: mix = gelu(acc + direct*xn) -> SMEM slots 0..3 ----
    char* smc = reinterpret_cast<char*>(smem);
    #pragma unroll
    for (int mt = 0; mt < 2; mt++) {
        #pragma unroll
        for (int h = 0; h < 2; h++) {
            const int ml = wm * 32 + mt * 16 + (lane >> 2) + h * 8;
            const size_t mg = mblock + ml;
            #pragma unroll
            for (int nt = 0; nt < 8; nt++) {
                const int nl = wn * 64 + nt * 8 + (lane & 3) * 2;
                float v0 = acc[mt][nt][h * 2], v1 = acc[mt][nt][h * 2 + 1];
                uint32_t hv = *reinterpret_cast<const uint32_t*>(xn + mg * 256 + nl);
                __half2 xh = *reinterpret_cast<__half2*>(&hv);
                float x0 = __half2float(__low2half(xh));
                float x1 = __half2float(__high2half(xh));
                float2 dd = *reinterpret_cast<const float2*>(direct + nl);
                float o0 = gelu_tanh(v0 + dd.x * x0);
                float o1 = gelu_tanh(v1 + dd.y * x1);
                *reinterpret_cast<uint32_t*>(
                    smc + (nl >> 6) * ASLOT + (ml * 72 + (nl & 63)) * 2) = pk2h(o0, o1);
            }
        }
    }

    #pragma unroll
    for (int i = 0; i < 2; i++)
        #pragma unroll
        for (int j = 0; j < 8; j++)
            #pragma unroll
            for (int q = 0; q < 4; q++) acc[i][j][q] = 0.0f;

    // ---- phase 2: mix (SMEM, slot s) x W2 (double-buffered) ----
    #pragma unroll
    for (int s = 0; s < 4; s++) {
        if (s < 3) { CP_WAIT(1); } else { CP_WAIT(0); }
        __syncthreads();                      // W2 + (s==0) mix writes visible
        mma_step(sbase + (uint32_t)s * ASLOT + a_rel, b_off + (uint32_t)(s & 1) * WS2);
        if (s < 2) {
            __syncthreads();                  // W slot s&1 readers done
            issue_w(gW2, s + 2);
        }
    }

    // ---- epilogue 2: out = x + acc + out_b ----
    #pragma unroll
    for (int mt = 0; mt < 2; mt++) {
        #pragma unroll
        for (int h = 0; h < 2; h++) {
            const size_t mg = mblock + wm * 32 + mt * 16 + (lane >> 2) + h * 8;
            #pragma unroll
            for (int nt = 0; nt < 8; nt++) {
                const int n = wn * 64 + nt * 8 + (lane & 3) * 2;
                float v0 = acc[mt][nt][h * 2], v1 = acc[mt][nt][h * 2 + 1];
                float2 xv = *reinterpret_cast<const float2*>(x + mg * 256 + n);
                float2 bb2 = *reinterpret_cast<const float2*>(out_b + n);
                float2 o;
                o.x = xv.x + v0 + bb2.x;
                o.y = xv.y + v1 + bb2.y;
                *reinterpret_cast<float2*>(out + mg * 256 + n) = o;
            }
        }
    }
}

// ---------------- 3b. chunk-level scan (prefetch all carries) ----------------
__global__ void __launch_bounds__(256) scanB_kernel(const float* __restrict__ state0,
                                                    float* __restrict__ out) {
    int b = blockIdx.x, s = threadIdx.x;
    const float* cp = g_carry + (size_t)b * NCH * SS + s;
    float carr[NCH];
    #pragma unroll
    for (int ch = 0; ch < NCH; ch++) carr[ch] = cp[(size_t)ch * SS];
    float cL = g_cL[s];
    float run = state0[b * SS + s];
    float* s0 = g_S0 + (size_t)b * NCH * SS + s;
    #pragma unroll
    for (int ch = 0; ch < NCH; ch++) {
        s0[(size_t)ch * SS] = run;
        run = fmaf(cL, run, carr[ch]);
    }
    out[(size_t)MM * HH + (size_t)b * SS + s] = run;
}

// ---------------- launch ----------------
extern "C" void kernel_launch(void* const* d_in, const int* in_sizes, int n_in,
                              void* d_out, int out_size) {
    const float* x       = (const float*)d_in[0];
    const float* state0  = (const float*)d_in[1];
    const float* its     = (const float*)d_in[2];
    const float* sth     = (const float*)d_in[3];
    const float* direct  = (const float*)d_in[4];
    const float* a_diag  = (const float*)d_in[5];
    const float* g_diag  = (const float*)d_in[6];
    const float* dt      = (const float*)d_in[7];
    const float* norm_w  = (const float*)d_in[8];
    const float* norm_b  = (const float*)d_in[9];
    const float* out_w   = (const float*)d_in[10];
    const float* out_b   = (const float*)d_in[11];
    float* out = (float*)d_out;

    __half *xn, *u16, *wcat;
    cudaGetSymbolAddress((void**)&xn,   g_xn);
    cudaGetSymbolAddress((void**)&u16,  g_u);
    cudaGetSymbolAddress((void**)&wcat, g_wcat);

    cudaFuncSetAttribute(gemm0_kernel, cudaFuncAttributeMaxDynamicSharedMemorySize, GSMEM0);
    cudaFuncSetAttribute(gemm12_kernel, cudaFuncAttributeMaxDynamicSharedMemorySize, GSMEM12);

    wsplit_kernel<<<dim3(256, 3), 256>>>(its, sth, out_w, a_diag, g_diag, dt);
    ln_kernel<<<MM / 8, 256>>>(x, norm_w, norm_b);

    gemm0_kernel<<<dim3(2, MM / 128), 256, GSMEM0>>>(xn, wcat, u16);

    scanB_kernel<<<BB, 256>>>(state0, out);

    gemm12_kernel<<<MM / 64, 256, GSMEM12>>>(
        u16, wcat + (size_t)1 * 256 * 256, wcat + (size_t)2 * 256 * 256,
        direct, xn, x, out_b, out);
}